// round 12
// baseline (speedup 1.0000x reference)
#include <cuda_runtime.h>
#include <cuda_fp16.h>
#include <cstdint>
#include <math.h>

// Problem constants
#define BB 2
#define SS 2048
#define EE 1024
#define HH 16
#define DD 64
#define MROWS (BB*SS)          // 4096
#define KDIM 1024
#define N_QKV 3072

// ---------------------------------------------------------------------------
// Scratch (allocation-free: device globals) — fp16 hi/lo splits
// ---------------------------------------------------------------------------
__device__ __half g_qhi[BB*HH*SS*DD];
__device__ __half g_qlo[BB*HH*SS*DD];
__device__ __half g_khi[BB*HH*SS*DD];
__device__ __half g_klo[BB*HH*SS*DD];
__device__ __half g_vhi[BB*HH*SS*DD];          // V: hi only (1-pass PV)

__device__ __half g_hhi[MROWS*KDIM];           // hidden hi
__device__ __half g_hlo[MROWS*KDIM];           // hidden lo
__device__ __half g_ahi[MROWS*KDIM];           // attn-out (hi only; 1-pass proj)
__device__ __half g_wqkvThi[N_QKV*KDIM];       // w_attn^T hi
__device__ __half g_wqkvTlo[N_QKV*KDIM];       // w_attn^T lo (Q/K blocks only)
__device__ __half g_wprojThi[EE*KDIM];         // w_proj^T hi

// ---------------------------------------------------------------------------
// PTX helpers
// ---------------------------------------------------------------------------
__device__ __forceinline__ uint32_t smem_u32(const void* p) {
    uint32_t a;
    asm("{ .reg .u64 t; cvta.to.shared.u64 t, %1; cvt.u32.u64 %0, t; }"
        : "=r"(a) : "l"(p));
    return a;
}

__device__ __forceinline__ void ldm_x4(uint32_t& r0, uint32_t& r1,
                                       uint32_t& r2, uint32_t& r3,
                                       uint32_t addr) {
    asm volatile("ldmatrix.sync.aligned.m8n8.x4.shared.b16 {%0,%1,%2,%3}, [%4];"
                 : "=r"(r0), "=r"(r1), "=r"(r2), "=r"(r3) : "r"(addr));
}
__device__ __forceinline__ void ldm_x4_t(uint32_t& r0, uint32_t& r1,
                                         uint32_t& r2, uint32_t& r3,
                                         uint32_t addr) {
    asm volatile("ldmatrix.sync.aligned.m8n8.x4.trans.shared.b16 {%0,%1,%2,%3}, [%4];"
                 : "=r"(r0), "=r"(r1), "=r"(r2), "=r"(r3) : "r"(addr));
}

// fp32-accumulate MMA (main pass)
__device__ __forceinline__ void mma_f16(float* d, const uint32_t* a,
                                        uint32_t b0, uint32_t b1) {
    asm volatile(
        "mma.sync.aligned.m16n8k16.row.col.f32.f16.f16.f32 "
        "{%0,%1,%2,%3}, {%4,%5,%6,%7}, {%8,%9}, {%0,%1,%2,%3};"
        : "+f"(d[0]), "+f"(d[1]), "+f"(d[2]), "+f"(d[3])
        : "r"(a[0]), "r"(a[1]), "r"(a[2]), "r"(a[3]), "r"(b0), "r"(b1));
}
// fp16-accumulate MMA (correction passes; 2x rate if HW supports)
__device__ __forceinline__ void mma_f16h(uint32_t* d, const uint32_t* a,
                                         uint32_t b0, uint32_t b1) {
    asm volatile(
        "mma.sync.aligned.m16n8k16.row.col.f16.f16.f16.f16 "
        "{%0,%1}, {%2,%3,%4,%5}, {%6,%7}, {%0,%1};"
        : "+r"(d[0]), "+r"(d[1])
        : "r"(a[0]), "r"(a[1]), "r"(a[2]), "r"(a[3]), "r"(b0), "r"(b1));
}

__device__ __forceinline__ void cpa16(uint32_t dst, const void* src) {
    asm volatile("cp.async.cg.shared.global [%0], [%1], 16;"
                 :: "r"(dst), "l"(src));
}
#define CPA_COMMIT() asm volatile("cp.async.commit_group;" ::: "memory")
#define CPA_WAIT(n)  asm volatile("cp.async.wait_group %0;" :: "n"(n) : "memory")

__device__ __forceinline__ uint32_t packf16(float hi, float lo) {
    uint32_t d;
    asm("cvt.rn.f16x2.f32 %0, %1, %2;" : "=r"(d) : "f"(hi), "f"(lo));
    return d;
}
__device__ __forceinline__ float lof16(uint32_t u) {
    return __half2float(__ushort_as_half((unsigned short)(u & 0xffffu)));
}
__device__ __forceinline__ float hif16(uint32_t u) {
    return __half2float(__ushort_as_half((unsigned short)(u >> 16)));
}
// guaranteed-MUFU exp2
__device__ __forceinline__ float ex2(float x) {
    float y;
    asm("ex2.approx.f32 %0, %1;" : "=f"(y) : "f"(x));
    return y;
}

// ---------------------------------------------------------------------------
// Prep kernel 1: split fp32 -> fp16 hi/lo (hidden)
// ---------------------------------------------------------------------------
__global__ __launch_bounds__(256) void split_kernel(const float* __restrict__ x)
{
    size_t i0 = ((size_t)blockIdx.x * 256 + threadIdx.x) * 4;
    float4 v = *(const float4*)&x[i0];
    __half h0 = __float2half_rn(v.x);
    __half h1 = __float2half_rn(v.y);
    __half h2 = __float2half_rn(v.z);
    __half h3 = __float2half_rn(v.w);
    __half2 hp0; hp0.x = h0; hp0.y = h1;
    __half2 hp1; hp1.x = h2; hp1.y = h3;
    __half2 lp0;
    lp0.x = __float2half_rn(v.x - __half2float(h0));
    lp0.y = __float2half_rn(v.y - __half2float(h1));
    __half2 lp1;
    lp1.x = __float2half_rn(v.z - __half2float(h2));
    lp1.y = __float2half_rn(v.w - __half2float(h3));
    *(__half2*)&g_hhi[i0]     = hp0;
    *(__half2*)&g_hhi[i0 + 2] = hp1;
    *(__half2*)&g_hlo[i0]     = lp0;
    *(__half2*)&g_hlo[i0 + 2] = lp1;
}

// ---------------------------------------------------------------------------
// Prep kernel 2: W [K,N] row-major -> W^T [N,K] fp16 hi/lo
// ---------------------------------------------------------------------------
__global__ __launch_bounds__(256) void tsplit_kernel(const float* __restrict__ W,
                                                     int which, int N)
{
    __shared__ float t[32][33];
    int n0 = blockIdx.x * 32, k0 = blockIdx.y * 32;
    int tx = threadIdx.x & 31, ty = threadIdx.x >> 5;
#pragma unroll
    for (int r = 0; r < 32; r += 8)
        t[ty + r][tx] = W[(size_t)(k0 + ty + r) * N + n0 + tx];
    __syncthreads();
#pragma unroll
    for (int r = 0; r < 32; r += 8) {
        float v = t[tx][ty + r];
        __half h = __float2half_rn(v);
        size_t o = (size_t)(n0 + ty + r) * KDIM + k0 + tx;
        if (which) {
            g_wprojThi[o] = h;
        } else {
            g_wqkvThi[o] = h;
            g_wqkvTlo[o] = __float2half_rn(v - __half2float(h));
        }
    }
}

// ---------------------------------------------------------------------------
// Tensor-core GEMM: fp16 split, 3-stage cp.async, XOR-swizzled smem.
// p3 (QKV Q/K blocks): main pass fp32-acc + 2 correction passes fp16-acc.
// else 1-pass pure fp16 (V part of QKV; proj).
// ---------------------------------------------------------------------------
#define BK 32
#define GARR 8192u                        // one 128x32 fp16 array (bytes)
#define GSTAGE (4u * GARR)                // Ahi,Alo,Bhi,Blo = 32 KB
#define GEMM_SMEM_BYTES (3 * GSTAGE)      // 96 KB

__global__ __launch_bounds__(256, 2) void mma_gemm(const float* __restrict__ bias,
                                                   float* __restrict__ outp,
                                                   int mode)
{
    extern __shared__ __half gsm[];
    uint32_t sbase = smem_u32(gsm);
    uint32_t send = sbase + 3u * GSTAGE;

    const __half* Ahi = mode ? g_hhi : g_ahi;
    const __half* Alo = g_hlo;              // only used when p3
    const __half* Bhi = mode ? g_wqkvThi : g_wprojThi;
    const __half* Blo = g_wqkvTlo;          // only used when p3

    int tid = threadIdx.x;
    int wid = tid >> 5, lane = tid & 31;
    int warp_m = wid & 1, warp_n = wid >> 1;          // 2 x 4
    int m0 = blockIdx.y * 128, n0 = blockIdx.x * 128;
    const int p3 = (mode == 1) && (n0 < 2048);        // split path (Q/K)?

    float acc[4][4][4];
#pragma unroll
    for (int i = 0; i < 4; i++)
#pragma unroll
        for (int j = 0; j < 4; j++)
#pragma unroll
            for (int r = 0; r < 4; r++) acc[i][j][r] = 0.0f;

    // ---- load coordinates ----
    int lr = tid >> 1;
    int lv0 = (tid & 1) * 2;
    uint32_t swr = (uint32_t)((lr >> 1) & 3);
    uint32_t soff[2];
#pragma unroll
    for (int vv = 0; vv < 2; vv++) {
        uint32_t v = (uint32_t)(lv0 + vv);
        soff[vv] = (uint32_t)(lr * 64) + ((v ^ swr) << 4);
    }

    auto load_stage = [&](uint32_t sb, int kc) {
#pragma unroll
        for (int vv = 0; vv < 2; vv++) {
            int v = lv0 + vv;
            size_t asrc = (size_t)(m0 + lr) * KDIM + kc + v * 8;
            size_t bsrc = (size_t)(n0 + lr) * KDIM + kc + v * 8;
            uint32_t o = soff[vv];
            cpa16(sb + o,             Ahi + asrc);
            cpa16(sb + 2 * GARR + o,  Bhi + bsrc);
            if (p3) {
                cpa16(sb + GARR + o,     Alo + asrc);
                cpa16(sb + 3 * GARR + o, Blo + bsrc);
            }
        }
    };

    // ---- ldmatrix addressing (swizzled) ----
    int lrow = lane & 15, lcol = lane >> 4;
    uint32_t x = (uint32_t)((lrow >> 1) & 3);
    uint32_t coff0 = (((uint32_t)lcol ^ x) << 4);
    uint32_t coff1 = ((((uint32_t)lcol + 2u) ^ x) << 4);
    uint32_t aoff[4], boff[2];
#pragma unroll
    for (int mf = 0; mf < 4; mf++)
        aoff[mf] = (uint32_t)((warp_m * 64 + mf * 16 + lrow) * 64);
#pragma unroll
    for (int pf = 0; pf < 2; pf++)
        boff[pf] = (uint32_t)((warp_n * 32 + pf * 16 + lrow) * 64);

    load_stage(sbase, 0);
    CPA_COMMIT();
    load_stage(sbase + GSTAGE, BK);
    CPA_COMMIT();

    uint32_t sb_c = sbase;
    uint32_t sb_l = sbase + 2u * GSTAGE;

    const int NITER = KDIM / BK;      // 32
    for (int c = 0; c < NITER; c++) {
        if (c < NITER - 1) { CPA_WAIT(1); } else { CPA_WAIT(0); }
        __syncthreads();
        if (c + 2 < NITER) {
            load_stage(sb_l, (c + 2) * BK);
            CPA_COMMIT();
            sb_l += GSTAGE; if (sb_l == send) sb_l = sbase;
        }

        uint32_t sb = sb_c;
        sb_c += GSTAGE; if (sb_c == send) sb_c = sbase;

#pragma unroll
        for (int ki = 0; ki < 2; ki++) {
            uint32_t coff = ki ? coff1 : coff0;
            uint32_t bh[4][2];
#pragma unroll
            for (int pf = 0; pf < 2; pf++) {
                uint32_t r0, r1, r2, r3;
                ldm_x4(r0, r1, r2, r3, sb + 2 * GARR + boff[pf] + coff);
                bh[pf * 2 + 0][0] = r0; bh[pf * 2 + 0][1] = r2;
                bh[pf * 2 + 1][0] = r1; bh[pf * 2 + 1][1] = r3;
            }
            if (p3) {
                uint32_t bl[4][2];
#pragma unroll
                for (int pf = 0; pf < 2; pf++) {
                    uint32_t r0, r1, r2, r3;
                    ldm_x4(r0, r1, r2, r3, sb + 3 * GARR + boff[pf] + coff);
                    bl[pf * 2 + 0][0] = r0; bl[pf * 2 + 0][1] = r2;
                    bl[pf * 2 + 1][0] = r1; bl[pf * 2 + 1][1] = r3;
                }
#pragma unroll
                for (int mf = 0; mf < 4; mf++) {
                    uint32_t ah[4], al[4];
                    ldm_x4(ah[0], ah[1], ah[2], ah[3],
                           sb + aoff[mf] + coff);
                    ldm_x4(al[0], al[1], al[2], al[3],
                           sb + GARR + aoff[mf] + coff);
                    // main pass (fp32 acc)
#pragma unroll
                    for (int nf = 0; nf < 4; nf++)
                        mma_f16(acc[mf][nf], ah, bh[nf][0], bh[nf][1]);
                    // correction passes (fp16 acc, folded immediately)
                    uint32_t corr[4][2];
#pragma unroll
                    for (int nf = 0; nf < 4; nf++) {
                        corr[nf][0] = 0u; corr[nf][1] = 0u;
                    }
#pragma unroll
                    for (int nf = 0; nf < 4; nf++)
                        mma_f16h(corr[nf], al, bh[nf][0], bh[nf][1]);
#pragma unroll
                    for (int nf = 0; nf < 4; nf++)
                        mma_f16h(corr[nf], ah, bl[nf][0], bl[nf][1]);
#pragma unroll
                    for (int nf = 0; nf < 4; nf++) {
                        acc[mf][nf][0] += lof16(corr[nf][0]);
                        acc[mf][nf][1] += hif16(corr[nf][0]);
                        acc[mf][nf][2] += lof16(corr[nf][1]);
                        acc[mf][nf][3] += hif16(corr[nf][1]);
                    }
                }
            } else {
#pragma unroll
                for (int mf = 0; mf < 4; mf++) {
                    uint32_t ah[4];
                    ldm_x4(ah[0], ah[1], ah[2], ah[3],
                           sb + aoff[mf] + coff);
#pragma unroll
                    for (int nf = 0; nf < 4; nf++)
                        mma_f16(acc[mf][nf], ah, bh[nf][0], bh[nf][1]);
                }
            }
        }
    }

    // Epilogue
    int gID = lane >> 2, tcol = lane & 3;
#pragma unroll
    for (int mf = 0; mf < 4; mf++) {
#pragma unroll
        for (int nf = 0; nf < 4; nf++) {
            int c = n0 + warp_n * 32 + nf * 8 + tcol * 2;
            float2 bv = *(const float2*)&bias[c];
#pragma unroll
            for (int half = 0; half < 2; half++) {
                int r = m0 + warp_m * 64 + mf * 16 + gID + half * 8;
                float2 v;
                v.x = acc[mf][nf][half * 2 + 0] + bv.x;
                v.y = acc[mf][nf][half * 2 + 1] + bv.y;
                if (mode == 0) {
                    *(float2*)&outp[(size_t)r * EE + c] = v;
                } else {
                    int part = c >> 10, e = c & 1023, h = e >> 6, d0 = e & 63;
                    int b = r >> 11, s = r & 2047;
                    size_t base = (((size_t)(b * HH + h)) * SS + s) * DD + d0;
                    uint32_t hp = packf16(v.y, v.x);
                    if (part == 2) {
                        *(uint32_t*)&g_vhi[base] = hp;
                    } else {
                        uint32_t lp = packf16(v.y - hif16(hp), v.x - lof16(hp));
                        if (part == 0) {
                            *(uint32_t*)&g_qhi[base] = hp;
                            *(uint32_t*)&g_qlo[base] = lp;
                        } else {
                            *(uint32_t*)&g_khi[base] = hp;
                            *(uint32_t*)&g_klo[base] = lp;
                        }
                    }
                }
            }
        }
    }
}

// ---------------------------------------------------------------------------
// Tensor-core causal flash attention: QK^T main pass fp32-acc + 2 correction
// passes fp16-acc, PV 1-pass; Q fragments in registers; 2-stage cp.async K/V.
// ---------------------------------------------------------------------------
#define ALD 72
#define AQ_ELEMS (128 * ALD)
#define AKV_ARR (64 * ALD)
#define AKV_STAGE (3 * AKV_ARR)               // Khi,Klo,Vhi
#define OFF_KV0 (2 * AQ_ELEMS)
#define ATTN_SMEM_ELEMS (2 * AQ_ELEMS + 2 * AKV_STAGE)
#define ATTN_SMEM_BYTES (ATTN_SMEM_ELEMS * 2)   // 92160 B

#define LOG2E 1.4426950408889634f

__global__ __launch_bounds__(256, 2) void attn_mma_kernel()
{
    extern __shared__ __half dsm[];
    __half* Qhi_s = dsm;
    __half* Qlo_s = dsm + AQ_ELEMS;
    uint32_t kvbase = smem_u32(dsm + OFF_KV0);

    int qt = gridDim.x - 1 - blockIdx.x;        // big tiles first
    int h  = blockIdx.y;
    int b  = blockIdx.z;
    int tid = threadIdx.x, wid = tid >> 5, lane = tid & 31;

    size_t bh = ((size_t)(b * HH + h)) * SS * DD;
    const __half* Qhg = g_qhi + bh;
    const __half* Qlg = g_qlo + bh;
    const __half* Khg = g_khi + bh;
    const __half* Klg = g_klo + bh;
    const __half* Vhg = g_vhi + bh;

    int q0 = qt * 128;

    // Q tile into smem
#pragma unroll
    for (int t = 0; t < 4; t++) {
        int i = tid + t * 256;
        int r = i >> 3, v = i & 7;
        size_t src = (size_t)(q0 + r) * DD + v * 8;
        uint32_t so = (uint32_t)(r * ALD + v * 8);
        *(uint4*)&Qhi_s[so] = *(const uint4*)(Qhg + src);
        *(uint4*)&Qlo_s[so] = *(const uint4*)(Qlg + src);
    }

    auto load_kv = [&](int st, int k0) {
        uint32_t sb = kvbase + (uint32_t)(st * AKV_STAGE * 2);
#pragma unroll
        for (int t = 0; t < 2; t++) {
            int i = tid + t * 256;
            int r = i >> 3, v = i & 7;
            size_t src = (size_t)(k0 + r) * DD + v * 8;
            uint32_t o = (uint32_t)((r * ALD + v * 8) * 2);
            cpa16(sb + o,                   Khg + src);
            cpa16(sb + AKV_ARR * 2 + o,     Klg + src);
            cpa16(sb + 2 * AKV_ARR * 2 + o, Vhg + src);
        }
    };

    load_kv(0, 0);
    CPA_COMMIT();

    int lrow = lane & 15, lcol = lane >> 4;
    uint32_t qb_hi = smem_u32(Qhi_s) +
        (uint32_t)(((wid * 16 + lrow) * ALD + lcol * 8) * 2);
    uint32_t qb_lo = qb_hi + (uint32_t)(AQ_ELEMS * 2);
    uint32_t kvo = (uint32_t)((lrow * ALD + lcol * 8) * 2);

    // Hoist Q fragments into registers
    __syncthreads();
    uint32_t qh[4][4], ql[4][4];
#pragma unroll
    for (int ks = 0; ks < 4; ks++) {
        ldm_x4(qh[ks][0], qh[ks][1], qh[ks][2], qh[ks][3],
               qb_hi + (uint32_t)(ks * 32));
        ldm_x4(ql[ks][0], ql[ks][1], ql[ks][2], ql[ks][3],
               qb_lo + (uint32_t)(ks * 32));
    }

    float o[8][4];
#pragma unroll
    for (int j = 0; j < 8; j++)
#pragma unroll
        for (int e = 0; e < 4; e++) o[j][e] = 0.0f;
    float m_[2] = {-1e30f, -1e30f}, l_[2] = {0.0f, 0.0f};

    int row0 = q0 + wid * 16 + (lane >> 2);
    const float scale2 = (1.0f / 16.0f) * LOG2E;
    const float maskv = -10000.0f * LOG2E;

    int ktmax = 2 * qt + 1;

    for (int kt = 0; kt <= ktmax; kt++) {
        CPA_WAIT(0);
        __syncthreads();
        if (kt + 1 <= ktmax) {
            load_kv((kt + 1) & 1, (kt + 1) * 64);
            CPA_COMMIT();
        }

        uint32_t sb = kvbase + (uint32_t)((kt & 1) * AKV_STAGE * 2);
        uint32_t kb_hi = sb + kvo;
        uint32_t kb_lo = sb + AKV_ARR * 2 + kvo;
        uint32_t vb_hi = sb + 2 * AKV_ARR * 2 + kvo;
        int k0 = kt * 64;

        float s[8][4];
#pragma unroll
        for (int nf = 0; nf < 8; nf++)
#pragma unroll
            for (int e = 0; e < 4; e++) s[nf][e] = 0.0f;

        // S = Q K^T: main fp32-acc + corrections fp16-acc
#pragma unroll
        for (int g = 0; g < 4; g++) {
            uint32_t corr0[2] = {0u, 0u};
            uint32_t corr1[2] = {0u, 0u};
#pragma unroll
            for (int ks = 0; ks < 4; ks++) {
                uint32_t off = (uint32_t)((g * 16 * ALD + ks * 16) * 2);
                uint32_t r0, r1, r2, r3, t0, t1, t2, t3;
                ldm_x4(r0, r1, r2, r3, kb_hi + off);
                ldm_x4(t0, t1, t2, t3, kb_lo + off);
                mma_f16(s[2 * g],     qh[ks], r0, r2);
                mma_f16(s[2 * g + 1], qh[ks], r1, r3);
                mma_f16h(corr0, ql[ks], r0, r2);
                mma_f16h(corr1, ql[ks], r1, r3);
                mma_f16h(corr0, qh[ks], t0, t2);
                mma_f16h(corr1, qh[ks], t1, t3);
            }
            s[2 * g][0] += lof16(corr0[0]);
            s[2 * g][1] += hif16(corr0[0]);
            s[2 * g][2] += lof16(corr0[1]);
            s[2 * g][3] += hif16(corr0[1]);
            s[2 * g + 1][0] += lof16(corr1[0]);
            s[2 * g + 1][1] += hif16(corr1[0]);
            s[2 * g + 1][2] += lof16(corr1[1]);
            s[2 * g + 1][3] += hif16(corr1[1]);
        }

        if (kt >= ktmax - 1) {
#pragma unroll
            for (int nf = 0; nf < 8; nf++) {
                int cb = k0 + nf * 8 + (lane & 3) * 2;
#pragma unroll
                for (int e = 0; e < 4; e++) {
                    int col = cb + (e & 1);
                    int row = (e < 2) ? row0 : row0 + 8;
                    float v = s[nf][e] * scale2;
                    s[nf][e] = (col > row) ? maskv : v;
                }
            }
        } else {
#pragma unroll
            for (int nf = 0; nf < 8; nf++)
#pragma unroll
                for (int e = 0; e < 4; e++) s[nf][e] *= scale2;
        }

        // online softmax (log2 domain, MUFU exp2)
#pragma unroll
        for (int i = 0; i < 2; i++) {
            float mx = -1e30f;
#pragma unroll
            for (int nf = 0; nf < 8; nf++)
                mx = fmaxf(mx, fmaxf(s[nf][2 * i], s[nf][2 * i + 1]));
            mx = fmaxf(mx, __shfl_xor_sync(0xffffffffu, mx, 1));
            mx = fmaxf(mx, __shfl_xor_sync(0xffffffffu, mx, 2));
            float mn = fmaxf(m_[i], mx);
            float alpha = ex2(m_[i] - mn);
            float sum = 0.0f;
#pragma unroll
            for (int nf = 0; nf < 8; nf++) {
                float p0 = ex2(s[nf][2 * i] - mn);
                float p1 = ex2(s[nf][2 * i + 1] - mn);
                s[nf][2 * i] = p0; s[nf][2 * i + 1] = p1;
                sum += p0 + p1;
            }
            sum += __shfl_xor_sync(0xffffffffu, sum, 1);
            sum += __shfl_xor_sync(0xffffffffu, sum, 2);
            l_[i] = l_[i] * alpha + sum;
            m_[i] = mn;
#pragma unroll
            for (int j = 0; j < 8; j++) {
                o[j][2 * i] *= alpha; o[j][2 * i + 1] *= alpha;
            }
        }

        // O += P V  (1-pass: P hi only, V hi only)
#pragma unroll
        for (int c = 0; c < 4; c++) {
            uint32_t aph[4];
            aph[0] = packf16(s[2 * c][1], s[2 * c][0]);
            aph[1] = packf16(s[2 * c][3], s[2 * c][2]);
            aph[2] = packf16(s[2 * c + 1][1], s[2 * c + 1][0]);
            aph[3] = packf16(s[2 * c + 1][3], s[2 * c + 1][2]);
#pragma unroll
            for (int g = 0; g < 4; g++) {
                uint32_t off = (uint32_t)((c * 16 * ALD + g * 16) * 2);
                uint32_t r0, r1, r2, r3;
                ldm_x4_t(r0, r1, r2, r3, vb_hi + off);
                mma_f16(o[2 * g],     aph, r0, r1);
                mma_f16(o[2 * g + 1], aph, r2, r3);
            }
        }
    }

    // epilogue: O/l -> fp16 (hi only) merged-head [B*S, E]
    float inv0 = 1.0f / l_[0], inv1 = 1.0f / l_[1];
    int d0 = (lane & 3) * 2;
    size_t rb0 = ((size_t)(b * SS + row0)) * EE + h * DD;
    size_t rb1 = rb0 + (size_t)8 * EE;
#pragma unroll
    for (int j = 0; j < 8; j++) {
        int d = j * 8 + d0;
        float v0 = o[j][0] * inv0, v1 = o[j][1] * inv0;
        float v2 = o[j][2] * inv1, v3 = o[j][3] * inv1;
        *(uint32_t*)&g_ahi[rb0 + d] = packf16(v1, v0);
        *(uint32_t*)&g_ahi[rb1 + d] = packf16(v3, v2);
    }
}

// ---------------------------------------------------------------------------
extern "C" void kernel_launch(void* const* d_in, const int* in_sizes, int n_in,
                              void* d_out, int out_size)
{
    const float* hidden = (const float*)d_in[0];   // [B,S,E]
    const float* w_attn = (const float*)d_in[1];   // [E, 3E]
    const float* b_attn = (const float*)d_in[2];   // [3E]
    const float* w_proj = (const float*)d_in[3];   // [E, E]
    const float* b_proj = (const float*)d_in[4];   // [E]
    float* out = (float*)d_out;                    // [B,S,E] fp32

    split_kernel<<<(MROWS * KDIM) / (256 * 4), 256>>>(hidden);
    tsplit_kernel<<<dim3(N_QKV / 32, KDIM / 32), 256>>>(w_attn, 0, N_QKV);
    tsplit_kernel<<<dim3(EE / 32, KDIM / 32), 256>>>(w_proj, 1, EE);

    cudaFuncSetAttribute(mma_gemm, cudaFuncAttributeMaxDynamicSharedMemorySize,
                         GEMM_SMEM_BYTES);
    mma_gemm<<<dim3(N_QKV / 128, MROWS / 128), 256, GEMM_SMEM_BYTES>>>(
        b_attn, nullptr, 1);

    cudaFuncSetAttribute(attn_mma_kernel,
                         cudaFuncAttributeMaxDynamicSharedMemorySize,
                         ATTN_SMEM_BYTES);
    attn_mma_kernel<<<dim3(SS / 128, HH, BB), 256, ATTN_SMEM_BYTES>>>();

    mma_gemm<<<dim3(EE / 128, MROWS / 128), 256, GEMM_SMEM_BYTES>>>(
        b_proj, out, 0);
}

// round 13
// speedup vs baseline: 1.1635x; 1.1635x over previous
#include <cuda_runtime.h>
#include <cuda_fp16.h>
#include <cstdint>
#include <math.h>

// Problem constants
#define BB 2
#define SS 2048
#define EE 1024
#define HH 16
#define DD 64
#define MROWS (BB*SS)          // 4096
#define KDIM 1024
#define N_QKV 3072

// ---------------------------------------------------------------------------
// Scratch (allocation-free: device globals) — fp16 hi/lo splits
// ---------------------------------------------------------------------------
__device__ __half g_qhi[BB*HH*SS*DD];
__device__ __half g_qlo[BB*HH*SS*DD];
__device__ __half g_khi[BB*HH*SS*DD];
__device__ __half g_klo[BB*HH*SS*DD];
__device__ __half g_vhi[BB*HH*SS*DD];          // V: hi only (1-pass PV)

__device__ __half g_hhi[MROWS*KDIM];           // hidden hi
__device__ __half g_hlo[MROWS*KDIM];           // hidden lo
__device__ __half g_ahi[MROWS*KDIM];           // attn-out (hi only; 1-pass proj)
__device__ __half g_wqkvThi[N_QKV*KDIM];       // w_attn^T hi
__device__ __half g_wqkvTlo[N_QKV*KDIM];       // w_attn^T lo (Q/K blocks only)
__device__ __half g_wprojThi[EE*KDIM];         // w_proj^T hi

// ---------------------------------------------------------------------------
// PTX helpers
// ---------------------------------------------------------------------------
__device__ __forceinline__ uint32_t smem_u32(const void* p) {
    uint32_t a;
    asm("{ .reg .u64 t; cvta.to.shared.u64 t, %1; cvt.u32.u64 %0, t; }"
        : "=r"(a) : "l"(p));
    return a;
}

__device__ __forceinline__ void ldm_x4(uint32_t& r0, uint32_t& r1,
                                       uint32_t& r2, uint32_t& r3,
                                       uint32_t addr) {
    asm volatile("ldmatrix.sync.aligned.m8n8.x4.shared.b16 {%0,%1,%2,%3}, [%4];"
                 : "=r"(r0), "=r"(r1), "=r"(r2), "=r"(r3) : "r"(addr));
}
__device__ __forceinline__ void ldm_x4_t(uint32_t& r0, uint32_t& r1,
                                         uint32_t& r2, uint32_t& r3,
                                         uint32_t addr) {
    asm volatile("ldmatrix.sync.aligned.m8n8.x4.trans.shared.b16 {%0,%1,%2,%3}, [%4];"
                 : "=r"(r0), "=r"(r1), "=r"(r2), "=r"(r3) : "r"(addr));
}

__device__ __forceinline__ void mma_f16(float* d, const uint32_t* a,
                                        uint32_t b0, uint32_t b1) {
    asm volatile(
        "mma.sync.aligned.m16n8k16.row.col.f32.f16.f16.f32 "
        "{%0,%1,%2,%3}, {%4,%5,%6,%7}, {%8,%9}, {%0,%1,%2,%3};"
        : "+f"(d[0]), "+f"(d[1]), "+f"(d[2]), "+f"(d[3])
        : "r"(a[0]), "r"(a[1]), "r"(a[2]), "r"(a[3]), "r"(b0), "r"(b1));
}

__device__ __forceinline__ void cpa16(uint32_t dst, const void* src) {
    asm volatile("cp.async.cg.shared.global [%0], [%1], 16;"
                 :: "r"(dst), "l"(src));
}
#define CPA_COMMIT() asm volatile("cp.async.commit_group;" ::: "memory")
#define CPA_WAIT(n)  asm volatile("cp.async.wait_group %0;" :: "n"(n) : "memory")

__device__ __forceinline__ uint32_t packf16(float hi, float lo) {
    uint32_t d;
    asm("cvt.rn.f16x2.f32 %0, %1, %2;" : "=r"(d) : "f"(hi), "f"(lo));
    return d;
}
__device__ __forceinline__ float lof16(uint32_t u) {
    return __half2float(__ushort_as_half((unsigned short)(u & 0xffffu)));
}
__device__ __forceinline__ float hif16(uint32_t u) {
    return __half2float(__ushort_as_half((unsigned short)(u >> 16)));
}
// guaranteed-MUFU exp2
__device__ __forceinline__ float ex2(float x) {
    float y;
    asm("ex2.approx.f32 %0, %1;" : "=f"(y) : "f"(x));
    return y;
}

// ---------------------------------------------------------------------------
// Fused prep kernel (one launch):
//   bid [0, 4096):        split hidden fp32 -> fp16 hi/lo
//   bid [4096, 7168):     w_attn^T hi/lo   (3072 tiles of 32x32)
//   bid [7168, 8192):     w_proj^T hi      (1024 tiles of 32x32)
// ---------------------------------------------------------------------------
#define PREP_SPLIT_BLKS 4096
#define PREP_WA_BLKS    3072
#define PREP_TOTAL_BLKS 8192

__global__ __launch_bounds__(256) void prep_kernel(
    const float* __restrict__ x,
    const float* __restrict__ Wa,
    const float* __restrict__ Wp)
{
    __shared__ float t[32][33];
    int bid = blockIdx.x;
    if (bid < PREP_SPLIT_BLKS) {
        size_t i0 = ((size_t)bid * 256 + threadIdx.x) * 4;
        float4 v = *(const float4*)&x[i0];
        __half h0 = __float2half_rn(v.x);
        __half h1 = __float2half_rn(v.y);
        __half h2 = __float2half_rn(v.z);
        __half h3 = __float2half_rn(v.w);
        __half2 hp0; hp0.x = h0; hp0.y = h1;
        __half2 hp1; hp1.x = h2; hp1.y = h3;
        __half2 lp0;
        lp0.x = __float2half_rn(v.x - __half2float(h0));
        lp0.y = __float2half_rn(v.y - __half2float(h1));
        __half2 lp1;
        lp1.x = __float2half_rn(v.z - __half2float(h2));
        lp1.y = __float2half_rn(v.w - __half2float(h3));
        *(__half2*)&g_hhi[i0]     = hp0;
        *(__half2*)&g_hhi[i0 + 2] = hp1;
        *(__half2*)&g_hlo[i0]     = lp0;
        *(__half2*)&g_hlo[i0 + 2] = lp1;
        return;
    }
    // transpose-split branch
    int which, N, n0, k0;
    if (bid < PREP_SPLIT_BLKS + PREP_WA_BLKS) {
        int tt = bid - PREP_SPLIT_BLKS;
        which = 0; N = N_QKV;
        n0 = (tt % 96) * 32; k0 = (tt / 96) * 32;
    } else {
        int tt = bid - PREP_SPLIT_BLKS - PREP_WA_BLKS;
        which = 1; N = EE;
        n0 = (tt % 32) * 32; k0 = (tt / 32) * 32;
    }
    const float* W = which ? Wp : Wa;
    int tx = threadIdx.x & 31, ty = threadIdx.x >> 5;
#pragma unroll
    for (int r = 0; r < 32; r += 8)
        t[ty + r][tx] = W[(size_t)(k0 + ty + r) * N + n0 + tx];
    __syncthreads();
#pragma unroll
    for (int r = 0; r < 32; r += 8) {
        float v = t[tx][ty + r];
        __half h = __float2half_rn(v);
        size_t o = (size_t)(n0 + ty + r) * KDIM + k0 + tx;
        if (which) {
            g_wprojThi[o] = h;
        } else {
            g_wqkvThi[o] = h;
            g_wqkvTlo[o] = __float2half_rn(v - __half2float(h));
        }
    }
}

// ---------------------------------------------------------------------------
// Tensor-core GEMM: fp16 split, 3-stage cp.async, XOR-swizzled smem.
// 1-D grid with LPT ordering for mode 1: heavy (3-pass Q/K) tiles first.
// p3 = (mode==1 && n0<2048): 3-pass; else 1-pass pure fp16.
// ---------------------------------------------------------------------------
#define BK 32
#define GARR 8192u                        // one 128x32 fp16 array (bytes)
#define GSTAGE (4u * GARR)                // Ahi,Alo,Bhi,Blo = 32 KB
#define GEMM_SMEM_BYTES (3 * GSTAGE)      // 96 KB

__global__ __launch_bounds__(256, 2) void mma_gemm(const float* __restrict__ bias,
                                                   float* __restrict__ outp,
                                                   int mode)
{
    extern __shared__ __half gsm[];
    uint32_t sbase = smem_u32(gsm);
    uint32_t send = sbase + 3u * GSTAGE;

    const __half* Ahi = mode ? g_hhi : g_ahi;
    const __half* Alo = g_hlo;              // only used when p3
    const __half* Bhi = mode ? g_wqkvThi : g_wprojThi;
    const __half* Blo = g_wqkvTlo;          // only used when p3

    int tid = threadIdx.x;
    int wid = tid >> 5, lane = tid & 31;
    int warp_m = wid & 1, warp_n = wid >> 1;          // 2 x 4

    // 1-D grid decode; mode 1 uses LPT order (heavy 3-pass tiles first)
    int bid = blockIdx.x;
    int bx, by;
    if (mode) {
        if (bid < 512) { by = bid >> 4; bx = bid & 15; }       // Q/K tiles
        else { int tt = bid - 512; by = tt >> 3; bx = 16 + (tt & 7); }  // V
    } else {
        bx = bid & 7; by = bid >> 3;
    }
    int m0 = by * 128, n0 = bx * 128;
    const int p3 = (mode == 1) && (n0 < 2048);        // 3-pass (Q/K)?

    float acc[4][4][4];
#pragma unroll
    for (int i = 0; i < 4; i++)
#pragma unroll
        for (int j = 0; j < 4; j++)
#pragma unroll
            for (int r = 0; r < 4; r++) acc[i][j][r] = 0.0f;

    // ---- load coordinates ----
    int lr = tid >> 1;                 // row 0..127
    int lv0 = (tid & 1) * 2;           // logical vec 0 or 2
    uint32_t swr = (uint32_t)((lr >> 1) & 3);
    uint32_t soff[2];
#pragma unroll
    for (int vv = 0; vv < 2; vv++) {
        uint32_t v = (uint32_t)(lv0 + vv);
        soff[vv] = (uint32_t)(lr * 64) + ((v ^ swr) << 4);
    }

    auto load_stage = [&](uint32_t sb, int kc) {
#pragma unroll
        for (int vv = 0; vv < 2; vv++) {
            int v = lv0 + vv;
            size_t asrc = (size_t)(m0 + lr) * KDIM + kc + v * 8;
            size_t bsrc = (size_t)(n0 + lr) * KDIM + kc + v * 8;
            uint32_t o = soff[vv];
            cpa16(sb + o,             Ahi + asrc);
            cpa16(sb + 2 * GARR + o,  Bhi + bsrc);
            if (p3) {
                cpa16(sb + GARR + o,     Alo + asrc);
                cpa16(sb + 3 * GARR + o, Blo + bsrc);
            }
        }
    };

    // ---- ldmatrix addressing (swizzled) ----
    int lrow = lane & 15, lcol = lane >> 4;
    uint32_t x = (uint32_t)((lrow >> 1) & 3);
    uint32_t coff0 = (((uint32_t)lcol ^ x) << 4);
    uint32_t coff1 = ((((uint32_t)lcol + 2u) ^ x) << 4);
    uint32_t aoff[4], boff[2];
#pragma unroll
    for (int mf = 0; mf < 4; mf++)
        aoff[mf] = (uint32_t)((warp_m * 64 + mf * 16 + lrow) * 64);
#pragma unroll
    for (int pf = 0; pf < 2; pf++)
        boff[pf] = (uint32_t)((warp_n * 32 + pf * 16 + lrow) * 64);

    load_stage(sbase, 0);
    CPA_COMMIT();
    load_stage(sbase + GSTAGE, BK);
    CPA_COMMIT();

    uint32_t sb_c = sbase;                 // compute stage
    uint32_t sb_l = sbase + 2u * GSTAGE;   // next load stage

    const int NITER = KDIM / BK;      // 32
    for (int c = 0; c < NITER; c++) {
        if (c < NITER - 1) { CPA_WAIT(1); } else { CPA_WAIT(0); }
        __syncthreads();
        if (c + 2 < NITER) {
            load_stage(sb_l, (c + 2) * BK);
            CPA_COMMIT();
            sb_l += GSTAGE; if (sb_l == send) sb_l = sbase;
        }

        uint32_t sb = sb_c;
        sb_c += GSTAGE; if (sb_c == send) sb_c = sbase;

#pragma unroll
        for (int ki = 0; ki < 2; ki++) {
            uint32_t coff = ki ? coff1 : coff0;
            uint32_t ah[4][4];
#pragma unroll
            for (int mf = 0; mf < 4; mf++)
                ldm_x4(ah[mf][0], ah[mf][1], ah[mf][2], ah[mf][3],
                       sb + aoff[mf] + coff);
            uint32_t bh[4][2];
#pragma unroll
            for (int pf = 0; pf < 2; pf++) {
                uint32_t r0, r1, r2, r3;
                ldm_x4(r0, r1, r2, r3, sb + 2 * GARR + boff[pf] + coff);
                bh[pf * 2 + 0][0] = r0; bh[pf * 2 + 0][1] = r2;
                bh[pf * 2 + 1][0] = r1; bh[pf * 2 + 1][1] = r3;
            }
#pragma unroll
            for (int mf = 0; mf < 4; mf++)
#pragma unroll
                for (int nf = 0; nf < 4; nf++)
                    mma_f16(acc[mf][nf], ah[mf], bh[nf][0], bh[nf][1]);
            if (p3) {
                uint32_t al[4][4];
#pragma unroll
                for (int mf = 0; mf < 4; mf++)
                    ldm_x4(al[mf][0], al[mf][1], al[mf][2], al[mf][3],
                           sb + GARR + aoff[mf] + coff);
#pragma unroll
                for (int mf = 0; mf < 4; mf++)
#pragma unroll
                    for (int nf = 0; nf < 4; nf++)
                        mma_f16(acc[mf][nf], al[mf], bh[nf][0], bh[nf][1]);
                uint32_t bl[4][2];
#pragma unroll
                for (int pf = 0; pf < 2; pf++) {
                    uint32_t r0, r1, r2, r3;
                    ldm_x4(r0, r1, r2, r3, sb + 3 * GARR + boff[pf] + coff);
                    bl[pf * 2 + 0][0] = r0; bl[pf * 2 + 0][1] = r2;
                    bl[pf * 2 + 1][0] = r1; bl[pf * 2 + 1][1] = r3;
                }
#pragma unroll
                for (int mf = 0; mf < 4; mf++)
#pragma unroll
                    for (int nf = 0; nf < 4; nf++)
                        mma_f16(acc[mf][nf], ah[mf], bl[nf][0], bl[nf][1]);
            }
        }
    }

    // Epilogue
    int gID = lane >> 2, tcol = lane & 3;
#pragma unroll
    for (int mf = 0; mf < 4; mf++) {
#pragma unroll
        for (int nf = 0; nf < 4; nf++) {
            int c = n0 + warp_n * 32 + nf * 8 + tcol * 2;
            float2 bv = *(const float2*)&bias[c];
#pragma unroll
            for (int half = 0; half < 2; half++) {
                int r = m0 + warp_m * 64 + mf * 16 + gID + half * 8;
                float2 v;
                v.x = acc[mf][nf][half * 2 + 0] + bv.x;
                v.y = acc[mf][nf][half * 2 + 1] + bv.y;
                if (mode == 0) {
                    *(float2*)&outp[(size_t)r * EE + c] = v;
                } else {
                    int part = c >> 10, e = c & 1023, h = e >> 6, d0 = e & 63;
                    int b = r >> 11, s = r & 2047;
                    size_t base = (((size_t)(b * HH + h)) * SS + s) * DD + d0;
                    uint32_t hp = packf16(v.y, v.x);
                    if (part == 2) {
                        *(uint32_t*)&g_vhi[base] = hp;
                    } else {
                        uint32_t lp = packf16(v.y - hif16(hp), v.x - lof16(hp));
                        if (part == 0) {
                            *(uint32_t*)&g_qhi[base] = hp;
                            *(uint32_t*)&g_qlo[base] = lp;
                        } else {
                            *(uint32_t*)&g_khi[base] = hp;
                            *(uint32_t*)&g_klo[base] = lp;
                        }
                    }
                }
            }
        }
    }
}

// ---------------------------------------------------------------------------
// Tensor-core causal flash attention: QK^T 3-pass fp16 split, PV 1-pass,
// Q fragments hoisted to registers, 2-stage cp.async K/V, MUFU exp2.
// ---------------------------------------------------------------------------
#define ALD 72
#define AQ_ELEMS (128 * ALD)
#define AKV_ARR (64 * ALD)
#define AKV_STAGE (3 * AKV_ARR)               // Khi,Klo,Vhi
#define OFF_KV0 (2 * AQ_ELEMS)
#define ATTN_SMEM_ELEMS (2 * AQ_ELEMS + 2 * AKV_STAGE)
#define ATTN_SMEM_BYTES (ATTN_SMEM_ELEMS * 2)   // 92160 B

#define LOG2E 1.4426950408889634f

__global__ __launch_bounds__(256, 2) void attn_mma_kernel()
{
    extern __shared__ __half dsm[];
    __half* Qhi_s = dsm;
    __half* Qlo_s = dsm + AQ_ELEMS;
    uint32_t kvbase = smem_u32(dsm + OFF_KV0);

    int qt = gridDim.x - 1 - blockIdx.x;        // big tiles first
    int h  = blockIdx.y;
    int b  = blockIdx.z;
    int tid = threadIdx.x, wid = tid >> 5, lane = tid & 31;

    size_t bh = ((size_t)(b * HH + h)) * SS * DD;
    const __half* Qhg = g_qhi + bh;
    const __half* Qlg = g_qlo + bh;
    const __half* Khg = g_khi + bh;
    const __half* Klg = g_klo + bh;
    const __half* Vhg = g_vhi + bh;

    int q0 = qt * 128;

    // Q tile into smem
#pragma unroll
    for (int t = 0; t < 4; t++) {
        int i = tid + t * 256;
        int r = i >> 3, v = i & 7;
        size_t src = (size_t)(q0 + r) * DD + v * 8;
        uint32_t so = (uint32_t)(r * ALD + v * 8);
        *(uint4*)&Qhi_s[so] = *(const uint4*)(Qhg + src);
        *(uint4*)&Qlo_s[so] = *(const uint4*)(Qlg + src);
    }

    auto load_kv = [&](int st, int k0) {
        uint32_t sb = kvbase + (uint32_t)(st * AKV_STAGE * 2);
#pragma unroll
        for (int t = 0; t < 2; t++) {
            int i = tid + t * 256;
            int r = i >> 3, v = i & 7;
            size_t src = (size_t)(k0 + r) * DD + v * 8;
            uint32_t o = (uint32_t)((r * ALD + v * 8) * 2);
            cpa16(sb + o,                   Khg + src);
            cpa16(sb + AKV_ARR * 2 + o,     Klg + src);
            cpa16(sb + 2 * AKV_ARR * 2 + o, Vhg + src);
        }
    };

    load_kv(0, 0);
    CPA_COMMIT();

    int lrow = lane & 15, lcol = lane >> 4;
    uint32_t qb_hi = smem_u32(Qhi_s) +
        (uint32_t)(((wid * 16 + lrow) * ALD + lcol * 8) * 2);
    uint32_t qb_lo = qb_hi + (uint32_t)(AQ_ELEMS * 2);
    uint32_t kvo = (uint32_t)((lrow * ALD + lcol * 8) * 2);

    // Hoist Q fragments into registers (one-time)
    __syncthreads();
    uint32_t qh[4][4], ql[4][4];
#pragma unroll
    for (int ks = 0; ks < 4; ks++) {
        ldm_x4(qh[ks][0], qh[ks][1], qh[ks][2], qh[ks][3],
               qb_hi + (uint32_t)(ks * 32));
        ldm_x4(ql[ks][0], ql[ks][1], ql[ks][2], ql[ks][3],
               qb_lo + (uint32_t)(ks * 32));
    }

    float o[8][4];
#pragma unroll
    for (int j = 0; j < 8; j++)
#pragma unroll
        for (int e = 0; e < 4; e++) o[j][e] = 0.0f;
    float m_[2] = {-1e30f, -1e30f}, l_[2] = {0.0f, 0.0f};

    int row0 = q0 + wid * 16 + (lane >> 2);
    const float scale2 = (1.0f / 16.0f) * LOG2E;
    const float maskv = -10000.0f * LOG2E;

    int ktmax = 2 * qt + 1;

    for (int kt = 0; kt <= ktmax; kt++) {
        CPA_WAIT(0);
        __syncthreads();
        if (kt + 1 <= ktmax) {
            load_kv((kt + 1) & 1, (kt + 1) * 64);
            CPA_COMMIT();
        }

        uint32_t sb = kvbase + (uint32_t)((kt & 1) * AKV_STAGE * 2);
        uint32_t kb_hi = sb + kvo;
        uint32_t kb_lo = sb + AKV_ARR * 2 + kvo;
        uint32_t vb_hi = sb + 2 * AKV_ARR * 2 + kvo;
        int k0 = kt * 64;

        float s[8][4];
#pragma unroll
        for (int nf = 0; nf < 8; nf++)
#pragma unroll
            for (int e = 0; e < 4; e++) s[nf][e] = 0.0f;

#pragma unroll
        for (int ks = 0; ks < 4; ks++) {
#pragma unroll
            for (int g = 0; g < 4; g++) {
                uint32_t off = (uint32_t)((g * 16 * ALD + ks * 16) * 2);
                uint32_t r0, r1, r2, r3, t0, t1, t2, t3;
                ldm_x4(r0, r1, r2, r3, kb_hi + off);
                ldm_x4(t0, t1, t2, t3, kb_lo + off);
                mma_f16(s[2 * g],     qh[ks], r0, r2);
                mma_f16(s[2 * g + 1], qh[ks], r1, r3);
                mma_f16(s[2 * g],     ql[ks], r0, r2);
                mma_f16(s[2 * g + 1], ql[ks], r1, r3);
                mma_f16(s[2 * g],     qh[ks], t0, t2);
                mma_f16(s[2 * g + 1], qh[ks], t1, t3);
            }
        }

        if (kt >= ktmax - 1) {
#pragma unroll
            for (int nf = 0; nf < 8; nf++) {
                int cb = k0 + nf * 8 + (lane & 3) * 2;
#pragma unroll
                for (int e = 0; e < 4; e++) {
                    int col = cb + (e & 1);
                    int row = (e < 2) ? row0 : row0 + 8;
                    float v = s[nf][e] * scale2;
                    s[nf][e] = (col > row) ? maskv : v;
                }
            }
        } else {
#pragma unroll
            for (int nf = 0; nf < 8; nf++)
#pragma unroll
                for (int e = 0; e < 4; e++) s[nf][e] *= scale2;
        }

        // online softmax (log2 domain, MUFU exp2)
#pragma unroll
        for (int i = 0; i < 2; i++) {
            float mx = -1e30f;
#pragma unroll
            for (int nf = 0; nf < 8; nf++)
                mx = fmaxf(mx, fmaxf(s[nf][2 * i], s[nf][2 * i + 1]));
            mx = fmaxf(mx, __shfl_xor_sync(0xffffffffu, mx, 1));
            mx = fmaxf(mx, __shfl_xor_sync(0xffffffffu, mx, 2));
            float mn = fmaxf(m_[i], mx);
            float alpha = ex2(m_[i] - mn);
            float sum = 0.0f;
#pragma unroll
            for (int nf = 0; nf < 8; nf++) {
                float p0 = ex2(s[nf][2 * i] - mn);
                float p1 = ex2(s[nf][2 * i + 1] - mn);
                s[nf][2 * i] = p0; s[nf][2 * i + 1] = p1;
                sum += p0 + p1;
            }
            sum += __shfl_xor_sync(0xffffffffu, sum, 1);
            sum += __shfl_xor_sync(0xffffffffu, sum, 2);
            l_[i] = l_[i] * alpha + sum;
            m_[i] = mn;
#pragma unroll
            for (int j = 0; j < 8; j++) {
                o[j][2 * i] *= alpha; o[j][2 * i + 1] *= alpha;
            }
        }

        // O += P V  (1-pass: P hi only, V hi only)
#pragma unroll
        for (int c = 0; c < 4; c++) {
            uint32_t aph[4];
            aph[0] = packf16(s[2 * c][1], s[2 * c][0]);
            aph[1] = packf16(s[2 * c][3], s[2 * c][2]);
            aph[2] = packf16(s[2 * c + 1][1], s[2 * c + 1][0]);
            aph[3] = packf16(s[2 * c + 1][3], s[2 * c + 1][2]);
#pragma unroll
            for (int g = 0; g < 4; g++) {
                uint32_t off = (uint32_t)((c * 16 * ALD + g * 16) * 2);
                uint32_t r0, r1, r2, r3;
                ldm_x4_t(r0, r1, r2, r3, vb_hi + off);
                mma_f16(o[2 * g],     aph, r0, r1);
                mma_f16(o[2 * g + 1], aph, r2, r3);
            }
        }
    }

    // epilogue: O/l -> fp16 (hi only) merged-head [B*S, E]
    float inv0 = 1.0f / l_[0], inv1 = 1.0f / l_[1];
    int d0 = (lane & 3) * 2;
    size_t rb0 = ((size_t)(b * SS + row0)) * EE + h * DD;
    size_t rb1 = rb0 + (size_t)8 * EE;
#pragma unroll
    for (int j = 0; j < 8; j++) {
        int d = j * 8 + d0;
        float v0 = o[j][0] * inv0, v1 = o[j][1] * inv0;
        float v2 = o[j][2] * inv1, v3 = o[j][3] * inv1;
        *(uint32_t*)&g_ahi[rb0 + d] = packf16(v1, v0);
        *(uint32_t*)&g_ahi[rb1 + d] = packf16(v3, v2);
    }
}

// ---------------------------------------------------------------------------
extern "C" void kernel_launch(void* const* d_in, const int* in_sizes, int n_in,
                              void* d_out, int out_size)
{
    const float* hidden = (const float*)d_in[0];   // [B,S,E]
    const float* w_attn = (const float*)d_in[1];   // [E, 3E]
    const float* b_attn = (const float*)d_in[2];   // [3E]
    const float* w_proj = (const float*)d_in[3];   // [E, E]
    const float* b_proj = (const float*)d_in[4];   // [E]
    float* out = (float*)d_out;                    // [B,S,E] fp32

    // Fused prep: hidden split + both weight transposes in one launch
    prep_kernel<<<PREP_TOTAL_BLKS, 256>>>(hidden, w_attn, w_proj);

    // 1) QKV GEMM (LPT-ordered 1-D grid: heavy 3-pass tiles first)
    cudaFuncSetAttribute(mma_gemm, cudaFuncAttributeMaxDynamicSharedMemorySize,
                         GEMM_SMEM_BYTES);
    mma_gemm<<<768, 256, GEMM_SMEM_BYTES>>>(b_attn, nullptr, 1);

    // 2) Causal flash attention
    cudaFuncSetAttribute(attn_mma_kernel,
                         cudaFuncAttributeMaxDynamicSharedMemorySize,
                         ATTN_SMEM_BYTES);
    attn_mma_kernel<<<dim3(SS / 128, HH, BB), 256, ATTN_SMEM_BYTES>>>();

    // 3) Output projection -> d_out
    mma_gemm<<<256, 256, GEMM_SMEM_BYTES>>>(b_proj, out, 0);
}

// round 14
// speedup vs baseline: 1.1930x; 1.0253x over previous
#include <cuda_runtime.h>
#include <cuda_fp16.h>
#include <cstdint>
#include <math.h>

// Problem constants
#define BB 2
#define SS 2048
#define EE 1024
#define HH 16
#define DD 64
#define MROWS (BB*SS)          // 4096
#define KDIM 1024
#define N_QKV 3072

// ---------------------------------------------------------------------------
// Scratch (allocation-free: device globals) — fp16 hi/lo splits
// ---------------------------------------------------------------------------
__device__ __half g_qhi[BB*HH*SS*DD];
__device__ __half g_qlo[BB*HH*SS*DD];
__device__ __half g_khi[BB*HH*SS*DD];
__device__ __half g_klo[BB*HH*SS*DD];
__device__ __half g_vhi[BB*HH*SS*DD];          // V: hi only (1-pass PV)

__device__ __half g_hhi[MROWS*KDIM];           // hidden hi
__device__ __half g_hlo[MROWS*KDIM];           // hidden lo
__device__ __half g_ahi[MROWS*KDIM];           // attn-out (hi only; 1-pass proj)
__device__ __half g_wqkvThi[N_QKV*KDIM];       // w_attn^T hi
__device__ __half g_wqkvTlo[N_QKV*KDIM];       // w_attn^T lo (Q/K blocks only)
__device__ __half g_wprojThi[EE*KDIM];         // w_proj^T hi

// ---------------------------------------------------------------------------
// PTX helpers
// ---------------------------------------------------------------------------
__device__ __forceinline__ uint32_t smem_u32(const void* p) {
    uint32_t a;
    asm("{ .reg .u64 t; cvta.to.shared.u64 t, %1; cvt.u32.u64 %0, t; }"
        : "=r"(a) : "l"(p));
    return a;
}

__device__ __forceinline__ void ldm_x4(uint32_t& r0, uint32_t& r1,
                                       uint32_t& r2, uint32_t& r3,
                                       uint32_t addr) {
    asm volatile("ldmatrix.sync.aligned.m8n8.x4.shared.b16 {%0,%1,%2,%3}, [%4];"
                 : "=r"(r0), "=r"(r1), "=r"(r2), "=r"(r3) : "r"(addr));
}
__device__ __forceinline__ void ldm_x4_t(uint32_t& r0, uint32_t& r1,
                                         uint32_t& r2, uint32_t& r3,
                                         uint32_t addr) {
    asm volatile("ldmatrix.sync.aligned.m8n8.x4.trans.shared.b16 {%0,%1,%2,%3}, [%4];"
                 : "=r"(r0), "=r"(r1), "=r"(r2), "=r"(r3) : "r"(addr));
}

__device__ __forceinline__ void mma_f16(float* d, const uint32_t* a,
                                        uint32_t b0, uint32_t b1) {
    asm volatile(
        "mma.sync.aligned.m16n8k16.row.col.f32.f16.f16.f32 "
        "{%0,%1,%2,%3}, {%4,%5,%6,%7}, {%8,%9}, {%0,%1,%2,%3};"
        : "+f"(d[0]), "+f"(d[1]), "+f"(d[2]), "+f"(d[3])
        : "r"(a[0]), "r"(a[1]), "r"(a[2]), "r"(a[3]), "r"(b0), "r"(b1));
}

__device__ __forceinline__ void cpa16(uint32_t dst, const void* src) {
    asm volatile("cp.async.cg.shared.global [%0], [%1], 16;"
                 :: "r"(dst), "l"(src));
}
#define CPA_COMMIT() asm volatile("cp.async.commit_group;" ::: "memory")
#define CPA_WAIT(n)  asm volatile("cp.async.wait_group %0;" :: "n"(n) : "memory")

__device__ __forceinline__ uint32_t packf16(float hi, float lo) {
    uint32_t d;
    asm("cvt.rn.f16x2.f32 %0, %1, %2;" : "=r"(d) : "f"(hi), "f"(lo));
    return d;
}
__device__ __forceinline__ float lof16(uint32_t u) {
    return __half2float(__ushort_as_half((unsigned short)(u & 0xffffu)));
}
__device__ __forceinline__ float hif16(uint32_t u) {
    return __half2float(__ushort_as_half((unsigned short)(u >> 16)));
}
// guaranteed-MUFU exp2 (fp32)
__device__ __forceinline__ float ex2(float x) {
    float y;
    asm("ex2.approx.f32 %0, %1;" : "=f"(y) : "f"(x));
    return y;
}
// paired fp16 exp2 — one MUFU op for two elements
__device__ __forceinline__ uint32_t ex2h2(uint32_t x) {
    uint32_t y;
    asm("ex2.approx.f16x2 %0, %1;" : "=r"(y) : "r"(x));
    return y;
}

// ---------------------------------------------------------------------------
// Fused prep kernel (one launch)
// ---------------------------------------------------------------------------
#define PREP_SPLIT_BLKS 4096
#define PREP_WA_BLKS    3072
#define PREP_TOTAL_BLKS 8192

__global__ __launch_bounds__(256) void prep_kernel(
    const float* __restrict__ x,
    const float* __restrict__ Wa,
    const float* __restrict__ Wp)
{
    __shared__ float t[32][33];
    int bid = blockIdx.x;
    if (bid < PREP_SPLIT_BLKS) {
        size_t i0 = ((size_t)bid * 256 + threadIdx.x) * 4;
        float4 v = *(const float4*)&x[i0];
        __half h0 = __float2half_rn(v.x);
        __half h1 = __float2half_rn(v.y);
        __half h2 = __float2half_rn(v.z);
        __half h3 = __float2half_rn(v.w);
        __half2 hp0; hp0.x = h0; hp0.y = h1;
        __half2 hp1; hp1.x = h2; hp1.y = h3;
        __half2 lp0;
        lp0.x = __float2half_rn(v.x - __half2float(h0));
        lp0.y = __float2half_rn(v.y - __half2float(h1));
        __half2 lp1;
        lp1.x = __float2half_rn(v.z - __half2float(h2));
        lp1.y = __float2half_rn(v.w - __half2float(h3));
        *(__half2*)&g_hhi[i0]     = hp0;
        *(__half2*)&g_hhi[i0 + 2] = hp1;
        *(__half2*)&g_hlo[i0]     = lp0;
        *(__half2*)&g_hlo[i0 + 2] = lp1;
        return;
    }
    int which, N, n0, k0;
    if (bid < PREP_SPLIT_BLKS + PREP_WA_BLKS) {
        int tt = bid - PREP_SPLIT_BLKS;
        which = 0; N = N_QKV;
        n0 = (tt % 96) * 32; k0 = (tt / 96) * 32;
    } else {
        int tt = bid - PREP_SPLIT_BLKS - PREP_WA_BLKS;
        which = 1; N = EE;
        n0 = (tt % 32) * 32; k0 = (tt / 32) * 32;
    }
    const float* W = which ? Wp : Wa;
    int tx = threadIdx.x & 31, ty = threadIdx.x >> 5;
#pragma unroll
    for (int r = 0; r < 32; r += 8)
        t[ty + r][tx] = W[(size_t)(k0 + ty + r) * N + n0 + tx];
    __syncthreads();
#pragma unroll
    for (int r = 0; r < 32; r += 8) {
        float v = t[tx][ty + r];
        __half h = __float2half_rn(v);
        size_t o = (size_t)(n0 + ty + r) * KDIM + k0 + tx;
        if (which) {
            g_wprojThi[o] = h;
        } else {
            g_wqkvThi[o] = h;
            g_wqkvTlo[o] = __float2half_rn(v - __half2float(h));
        }
    }
}

// ---------------------------------------------------------------------------
// Tensor-core GEMM: fp16 split, 3-stage cp.async, XOR-swizzled smem.
// 1-D grid, LPT order for mode 1. p3 tiles 3-pass, else 1-pass.
// ---------------------------------------------------------------------------
#define BK 32
#define GARR 8192u
#define GSTAGE (4u * GARR)
#define GEMM_SMEM_BYTES (3 * GSTAGE)

__global__ __launch_bounds__(256, 2) void mma_gemm(const float* __restrict__ bias,
                                                   float* __restrict__ outp,
                                                   int mode)
{
    extern __shared__ __half gsm[];
    uint32_t sbase = smem_u32(gsm);
    uint32_t send = sbase + 3u * GSTAGE;

    const __half* Ahi = mode ? g_hhi : g_ahi;
    const __half* Alo = g_hlo;
    const __half* Bhi = mode ? g_wqkvThi : g_wprojThi;
    const __half* Blo = g_wqkvTlo;

    int tid = threadIdx.x;
    int wid = tid >> 5, lane = tid & 31;
    int warp_m = wid & 1, warp_n = wid >> 1;

    int bid = blockIdx.x;
    int bx, by;
    if (mode) {
        if (bid < 512) { by = bid >> 4; bx = bid & 15; }
        else { int tt = bid - 512; by = tt >> 3; bx = 16 + (tt & 7); }
    } else {
        bx = bid & 7; by = bid >> 3;
    }
    int m0 = by * 128, n0 = bx * 128;
    const int p3 = (mode == 1) && (n0 < 2048);

    float acc[4][4][4];
#pragma unroll
    for (int i = 0; i < 4; i++)
#pragma unroll
        for (int j = 0; j < 4; j++)
#pragma unroll
            for (int r = 0; r < 4; r++) acc[i][j][r] = 0.0f;

    int lr = tid >> 1;
    int lv0 = (tid & 1) * 2;
    uint32_t swr = (uint32_t)((lr >> 1) & 3);
    uint32_t soff[2];
#pragma unroll
    for (int vv = 0; vv < 2; vv++) {
        uint32_t v = (uint32_t)(lv0 + vv);
        soff[vv] = (uint32_t)(lr * 64) + ((v ^ swr) << 4);
    }

    auto load_stage = [&](uint32_t sb, int kc) {
#pragma unroll
        for (int vv = 0; vv < 2; vv++) {
            int v = lv0 + vv;
            size_t asrc = (size_t)(m0 + lr) * KDIM + kc + v * 8;
            size_t bsrc = (size_t)(n0 + lr) * KDIM + kc + v * 8;
            uint32_t o = soff[vv];
            cpa16(sb + o,             Ahi + asrc);
            cpa16(sb + 2 * GARR + o,  Bhi + bsrc);
            if (p3) {
                cpa16(sb + GARR + o,     Alo + asrc);
                cpa16(sb + 3 * GARR + o, Blo + bsrc);
            }
        }
    };

    int lrow = lane & 15, lcol = lane >> 4;
    uint32_t x = (uint32_t)((lrow >> 1) & 3);
    uint32_t coff0 = (((uint32_t)lcol ^ x) << 4);
    uint32_t coff1 = ((((uint32_t)lcol + 2u) ^ x) << 4);
    uint32_t aoff[4], boff[2];
#pragma unroll
    for (int mf = 0; mf < 4; mf++)
        aoff[mf] = (uint32_t)((warp_m * 64 + mf * 16 + lrow) * 64);
#pragma unroll
    for (int pf = 0; pf < 2; pf++)
        boff[pf] = (uint32_t)((warp_n * 32 + pf * 16 + lrow) * 64);

    load_stage(sbase, 0);
    CPA_COMMIT();
    load_stage(sbase + GSTAGE, BK);
    CPA_COMMIT();

    uint32_t sb_c = sbase;
    uint32_t sb_l = sbase + 2u * GSTAGE;

    const int NITER = KDIM / BK;
    for (int c = 0; c < NITER; c++) {
        if (c < NITER - 1) { CPA_WAIT(1); } else { CPA_WAIT(0); }
        __syncthreads();
        if (c + 2 < NITER) {
            load_stage(sb_l, (c + 2) * BK);
            CPA_COMMIT();
            sb_l += GSTAGE; if (sb_l == send) sb_l = sbase;
        }

        uint32_t sb = sb_c;
        sb_c += GSTAGE; if (sb_c == send) sb_c = sbase;

#pragma unroll
        for (int ki = 0; ki < 2; ki++) {
            uint32_t coff = ki ? coff1 : coff0;
            uint32_t ah[4][4];
#pragma unroll
            for (int mf = 0; mf < 4; mf++)
                ldm_x4(ah[mf][0], ah[mf][1], ah[mf][2], ah[mf][3],
                       sb + aoff[mf] + coff);
            uint32_t bh[4][2];
#pragma unroll
            for (int pf = 0; pf < 2; pf++) {
                uint32_t r0, r1, r2, r3;
                ldm_x4(r0, r1, r2, r3, sb + 2 * GARR + boff[pf] + coff);
                bh[pf * 2 + 0][0] = r0; bh[pf * 2 + 0][1] = r2;
                bh[pf * 2 + 1][0] = r1; bh[pf * 2 + 1][1] = r3;
            }
#pragma unroll
            for (int mf = 0; mf < 4; mf++)
#pragma unroll
                for (int nf = 0; nf < 4; nf++)
                    mma_f16(acc[mf][nf], ah[mf], bh[nf][0], bh[nf][1]);
            if (p3) {
                uint32_t al[4][4];
#pragma unroll
                for (int mf = 0; mf < 4; mf++)
                    ldm_x4(al[mf][0], al[mf][1], al[mf][2], al[mf][3],
                           sb + GARR + aoff[mf] + coff);
#pragma unroll
                for (int mf = 0; mf < 4; mf++)
#pragma unroll
                    for (int nf = 0; nf < 4; nf++)
                        mma_f16(acc[mf][nf], al[mf], bh[nf][0], bh[nf][1]);
                uint32_t bl[4][2];
#pragma unroll
                for (int pf = 0; pf < 2; pf++) {
                    uint32_t r0, r1, r2, r3;
                    ldm_x4(r0, r1, r2, r3, sb + 3 * GARR + boff[pf] + coff);
                    bl[pf * 2 + 0][0] = r0; bl[pf * 2 + 0][1] = r2;
                    bl[pf * 2 + 1][0] = r1; bl[pf * 2 + 1][1] = r3;
                }
#pragma unroll
                for (int mf = 0; mf < 4; mf++)
#pragma unroll
                    for (int nf = 0; nf < 4; nf++)
                        mma_f16(acc[mf][nf], ah[mf], bl[nf][0], bl[nf][1]);
            }
        }
    }

    // Epilogue
    int gID = lane >> 2, tcol = lane & 3;
#pragma unroll
    for (int mf = 0; mf < 4; mf++) {
#pragma unroll
        for (int nf = 0; nf < 4; nf++) {
            int c = n0 + warp_n * 32 + nf * 8 + tcol * 2;
            float2 bv = *(const float2*)&bias[c];
#pragma unroll
            for (int half = 0; half < 2; half++) {
                int r = m0 + warp_m * 64 + mf * 16 + gID + half * 8;
                float2 v;
                v.x = acc[mf][nf][half * 2 + 0] + bv.x;
                v.y = acc[mf][nf][half * 2 + 1] + bv.y;
                if (mode == 0) {
                    *(float2*)&outp[(size_t)r * EE + c] = v;
                } else {
                    int part = c >> 10, e = c & 1023, h = e >> 6, d0 = e & 63;
                    int b = r >> 11, s = r & 2047;
                    size_t base = (((size_t)(b * HH + h)) * SS + s) * DD + d0;
                    uint32_t hp = packf16(v.y, v.x);
                    if (part == 2) {
                        *(uint32_t*)&g_vhi[base] = hp;
                    } else {
                        uint32_t lp = packf16(v.y - hif16(hp), v.x - lof16(hp));
                        if (part == 0) {
                            *(uint32_t*)&g_qhi[base] = hp;
                            *(uint32_t*)&g_qlo[base] = lp;
                        } else {
                            *(uint32_t*)&g_khi[base] = hp;
                            *(uint32_t*)&g_klo[base] = lp;
                        }
                    }
                }
            }
        }
    }
}

// ---------------------------------------------------------------------------
// Tensor-core causal flash attention: QK^T 3-pass fp16 split, PV 1-pass,
// Q frags in registers, 2-stage cp.async K/V, f16x2 paired MUFU softmax.
// ---------------------------------------------------------------------------
#define ALD 72
#define AQ_ELEMS (128 * ALD)
#define AKV_ARR (64 * ALD)
#define AKV_STAGE (3 * AKV_ARR)               // Khi,Klo,Vhi
#define OFF_KV0 (2 * AQ_ELEMS)
#define ATTN_SMEM_ELEMS (2 * AQ_ELEMS + 2 * AKV_STAGE)
#define ATTN_SMEM_BYTES (ATTN_SMEM_ELEMS * 2)   // 92160 B

#define LOG2E 1.4426950408889634f

__global__ __launch_bounds__(256, 2) void attn_mma_kernel()
{
    extern __shared__ __half dsm[];
    __half* Qhi_s = dsm;
    __half* Qlo_s = dsm + AQ_ELEMS;
    uint32_t kvbase = smem_u32(dsm + OFF_KV0);

    int qt = gridDim.x - 1 - blockIdx.x;        // big tiles first
    int h  = blockIdx.y;
    int b  = blockIdx.z;
    int tid = threadIdx.x, wid = tid >> 5, lane = tid & 31;

    size_t bh = ((size_t)(b * HH + h)) * SS * DD;
    const __half* Qhg = g_qhi + bh;
    const __half* Qlg = g_qlo + bh;
    const __half* Khg = g_khi + bh;
    const __half* Klg = g_klo + bh;
    const __half* Vhg = g_vhi + bh;

    int q0 = qt * 128;

    // Q tile into smem
#pragma unroll
    for (int t = 0; t < 4; t++) {
        int i = tid + t * 256;
        int r = i >> 3, v = i & 7;
        size_t src = (size_t)(q0 + r) * DD + v * 8;
        uint32_t so = (uint32_t)(r * ALD + v * 8);
        *(uint4*)&Qhi_s[so] = *(const uint4*)(Qhg + src);
        *(uint4*)&Qlo_s[so] = *(const uint4*)(Qlg + src);
    }

    auto load_kv = [&](int st, int k0) {
        uint32_t sb = kvbase + (uint32_t)(st * AKV_STAGE * 2);
#pragma unroll
        for (int t = 0; t < 2; t++) {
            int i = tid + t * 256;
            int r = i >> 3, v = i & 7;
            size_t src = (size_t)(k0 + r) * DD + v * 8;
            uint32_t o = (uint32_t)((r * ALD + v * 8) * 2);
            cpa16(sb + o,                   Khg + src);
            cpa16(sb + AKV_ARR * 2 + o,     Klg + src);
            cpa16(sb + 2 * AKV_ARR * 2 + o, Vhg + src);
        }
    };

    load_kv(0, 0);
    CPA_COMMIT();

    int lrow = lane & 15, lcol = lane >> 4;
    uint32_t qb_hi = smem_u32(Qhi_s) +
        (uint32_t)(((wid * 16 + lrow) * ALD + lcol * 8) * 2);
    uint32_t qb_lo = qb_hi + (uint32_t)(AQ_ELEMS * 2);
    uint32_t kvo = (uint32_t)((lrow * ALD + lcol * 8) * 2);

    // Hoist Q fragments into registers (one-time)
    __syncthreads();
    uint32_t qh[4][4], ql[4][4];
#pragma unroll
    for (int ks = 0; ks < 4; ks++) {
        ldm_x4(qh[ks][0], qh[ks][1], qh[ks][2], qh[ks][3],
               qb_hi + (uint32_t)(ks * 32));
        ldm_x4(ql[ks][0], ql[ks][1], ql[ks][2], ql[ks][3],
               qb_lo + (uint32_t)(ks * 32));
    }

    float o[8][4];
#pragma unroll
    for (int j = 0; j < 8; j++)
#pragma unroll
        for (int e = 0; e < 4; e++) o[j][e] = 0.0f;
    float m_[2] = {-1e30f, -1e30f}, l_[2] = {0.0f, 0.0f};

    int row0 = q0 + wid * 16 + (lane >> 2);
    const float scale2 = (1.0f / 16.0f) * LOG2E;
    const float maskv = -10000.0f * LOG2E;

    int ktmax = 2 * qt + 1;

    for (int kt = 0; kt <= ktmax; kt++) {
        CPA_WAIT(0);
        __syncthreads();
        if (kt + 1 <= ktmax) {
            load_kv((kt + 1) & 1, (kt + 1) * 64);
            CPA_COMMIT();
        }

        uint32_t sb = kvbase + (uint32_t)((kt & 1) * AKV_STAGE * 2);
        uint32_t kb_hi = sb + kvo;
        uint32_t kb_lo = sb + AKV_ARR * 2 + kvo;
        uint32_t vb_hi = sb + 2 * AKV_ARR * 2 + kvo;
        int k0 = kt * 64;

        float s[8][4];
#pragma unroll
        for (int nf = 0; nf < 8; nf++)
#pragma unroll
            for (int e = 0; e < 4; e++) s[nf][e] = 0.0f;

#pragma unroll
        for (int ks = 0; ks < 4; ks++) {
#pragma unroll
            for (int g = 0; g < 4; g++) {
                uint32_t off = (uint32_t)((g * 16 * ALD + ks * 16) * 2);
                uint32_t r0, r1, r2, r3, t0, t1, t2, t3;
                ldm_x4(r0, r1, r2, r3, kb_hi + off);
                ldm_x4(t0, t1, t2, t3, kb_lo + off);
                mma_f16(s[2 * g],     qh[ks], r0, r2);
                mma_f16(s[2 * g + 1], qh[ks], r1, r3);
                mma_f16(s[2 * g],     ql[ks], r0, r2);
                mma_f16(s[2 * g + 1], ql[ks], r1, r3);
                mma_f16(s[2 * g],     qh[ks], t0, t2);
                mma_f16(s[2 * g + 1], qh[ks], t1, t3);
            }
        }

        if (kt >= ktmax - 1) {
#pragma unroll
            for (int nf = 0; nf < 8; nf++) {
                int cb = k0 + nf * 8 + (lane & 3) * 2;
#pragma unroll
                for (int e = 0; e < 4; e++) {
                    int col = cb + (e & 1);
                    int row = (e < 2) ? row0 : row0 + 8;
                    float v = s[nf][e] * scale2;
                    s[nf][e] = (col > row) ? maskv : v;
                }
            }
        } else {
#pragma unroll
            for (int nf = 0; nf < 8; nf++)
#pragma unroll
                for (int e = 0; e < 4; e++) s[nf][e] *= scale2;
        }

        // online softmax (log2 domain): paired f16x2 exp, p stored as
        // PV A-operand fragments directly. ps[i][nf] = (p_hi, p_lo) pair.
        uint32_t ps[2][8];
#pragma unroll
        for (int i = 0; i < 2; i++) {
            float mx = -1e30f;
#pragma unroll
            for (int nf = 0; nf < 8; nf++)
                mx = fmaxf(mx, fmaxf(s[nf][2 * i], s[nf][2 * i + 1]));
            mx = fmaxf(mx, __shfl_xor_sync(0xffffffffu, mx, 1));
            mx = fmaxf(mx, __shfl_xor_sync(0xffffffffu, mx, 2));
            float mn = fmaxf(m_[i], mx);
            float alpha = ex2(m_[i] - mn);
#pragma unroll
            for (int nf = 0; nf < 8; nf++)
                ps[i][nf] = ex2h2(packf16(s[nf][2 * i + 1] - mn,
                                          s[nf][2 * i] - mn));
            float sum = 0.0f;
#pragma unroll
            for (int nf = 0; nf < 8; nf++)
                sum += lof16(ps[i][nf]) + hif16(ps[i][nf]);
            sum += __shfl_xor_sync(0xffffffffu, sum, 1);
            sum += __shfl_xor_sync(0xffffffffu, sum, 2);
            l_[i] = l_[i] * alpha + sum;
            m_[i] = mn;
#pragma unroll
            for (int j = 0; j < 8; j++) {
                o[j][2 * i] *= alpha; o[j][2 * i + 1] *= alpha;
            }
        }

        // O += P V  (1-pass; P fragments = ps pairs, no repack needed)
#pragma unroll
        for (int c = 0; c < 4; c++) {
            uint32_t aph[4];
            aph[0] = ps[0][2 * c];
            aph[1] = ps[1][2 * c];
            aph[2] = ps[0][2 * c + 1];
            aph[3] = ps[1][2 * c + 1];
#pragma unroll
            for (int g = 0; g < 4; g++) {
                uint32_t off = (uint32_t)((c * 16 * ALD + g * 16) * 2);
                uint32_t r0, r1, r2, r3;
                ldm_x4_t(r0, r1, r2, r3, vb_hi + off);
                mma_f16(o[2 * g],     aph, r0, r1);
                mma_f16(o[2 * g + 1], aph, r2, r3);
            }
        }
    }

    // epilogue: O/l -> fp16 (hi only) merged-head [B*S, E]
    float inv0 = 1.0f / l_[0], inv1 = 1.0f / l_[1];
    int d0 = (lane & 3) * 2;
    size_t rb0 = ((size_t)(b * SS + row0)) * EE + h * DD;
    size_t rb1 = rb0 + (size_t)8 * EE;
#pragma unroll
    for (int j = 0; j < 8; j++) {
        int d = j * 8 + d0;
        float v0 = o[j][0] * inv0, v1 = o[j][1] * inv0;
        float v2 = o[j][2] * inv1, v3 = o[j][3] * inv1;
        *(uint32_t*)&g_ahi[rb0 + d] = packf16(v1, v0);
        *(uint32_t*)&g_ahi[rb1 + d] = packf16(v3, v2);
    }
}

// ---------------------------------------------------------------------------
extern "C" void kernel_launch(void* const* d_in, const int* in_sizes, int n_in,
                              void* d_out, int out_size)
{
    const float* hidden = (const float*)d_in[0];   // [B,S,E]
    const float* w_attn = (const float*)d_in[1];   // [E, 3E]
    const float* b_attn = (const float*)d_in[2];   // [3E]
    const float* w_proj = (const float*)d_in[3];   // [E, E]
    const float* b_proj = (const float*)d_in[4];   // [E]
    float* out = (float*)d_out;                    // [B,S,E] fp32

    prep_kernel<<<PREP_TOTAL_BLKS, 256>>>(hidden, w_attn, w_proj);

    cudaFuncSetAttribute(mma_gemm, cudaFuncAttributeMaxDynamicSharedMemorySize,
                         GEMM_SMEM_BYTES);
    mma_gemm<<<768, 256, GEMM_SMEM_BYTES>>>(b_attn, nullptr, 1);

    cudaFuncSetAttribute(attn_mma_kernel,
                         cudaFuncAttributeMaxDynamicSharedMemorySize,
                         ATTN_SMEM_BYTES);
    attn_mma_kernel<<<dim3(SS / 128, HH, BB), 256, ATTN_SMEM_BYTES>>>();

    mma_gemm<<<256, 256, GEMM_SMEM_BYTES>>>(b_proj, out, 0);
}